// round 2
// baseline (speedup 1.0000x reference)
#include <cuda_runtime.h>

#define D 128
#define M_KEYS 16384          // B*S*T
#define N_ANCH 12288          // B*S*(T-1)
#define TOTAL_ELEMS 2097152   // B*S*T*D
#define REG_BLOCKS 512
#define INV_TEMP 10.0f

// Scratch (allocation-free rule: __device__ globals)
__device__ float g_keys[M_KEYS * D];   // normalized keys, 8MB
__device__ float g_norm[M_KEYS];       // row norms of hiddens
__device__ float g_ce[N_ANCH];         // per-anchor CE
__device__ float g_psp[REG_BLOCKS];    // spike partial sums
__device__ float g_pmem[REG_BLOCKS];   // mem^2 partial sums

// ---------------------------------------------------------------------------
// Kernel 1: L2-normalize all M hidden rows, record norms. 1 warp per row.
// ---------------------------------------------------------------------------
__global__ void __launch_bounds__(256) normalize_kernel(const float* __restrict__ hid) {
    int row  = (blockIdx.x * blockDim.x + threadIdx.x) >> 5;
    int lane = threadIdx.x & 31;
    if (row >= M_KEYS) return;
    float4 v = ((const float4*)(hid + (size_t)row * D))[lane]; // 32 lanes * 4 = 128
    float ss = v.x*v.x + v.y*v.y + v.z*v.z + v.w*v.w;
    #pragma unroll
    for (int o = 16; o; o >>= 1) ss += __shfl_xor_sync(0xffffffffu, ss, o);
    float nrm = fmaxf(sqrtf(ss), 1e-12f);   // matches F.normalize eps
    float inv = 1.0f / nrm;
    float4 o4 = make_float4(v.x*inv, v.y*inv, v.z*inv, v.w*inv);
    ((float4*)(g_keys + (size_t)row * D))[lane] = o4;
    if (lane == 0) g_norm[row] = nrm;
}

// ---------------------------------------------------------------------------
// Kernel 2: spike sum + mem^2 sum, per-block partials (deterministic).
// ---------------------------------------------------------------------------
__global__ void __launch_bounds__(256) reg_kernel(const float* __restrict__ sp,
                                                  const float* __restrict__ mem) {
    __shared__ float s1[256];
    __shared__ float s2[256];
    int tid = threadIdx.x;
    float a = 0.f, b = 0.f;
    const int n4 = TOTAL_ELEMS / 4;
    for (int i = blockIdx.x * 256 + tid; i < n4; i += REG_BLOCKS * 256) {
        float4 v = ((const float4*)sp)[i];
        a += (v.x + v.y) + (v.z + v.w);
        float4 w = ((const float4*)mem)[i];
        b += (w.x*w.x + w.y*w.y) + (w.z*w.z + w.w*w.w);
    }
    s1[tid] = a; s2[tid] = b;
    __syncthreads();
    for (int s = 128; s; s >>= 1) {
        if (tid < s) { s1[tid] += s1[tid + s]; s2[tid] += s2[tid + s]; }
        __syncthreads();
    }
    if (tid == 0) { g_psp[blockIdx.x] = s1[0]; g_pmem[blockIdx.x] = s2[0]; }
}

// ---------------------------------------------------------------------------
// Kernel 3: fused GEMM + fixed-shift logsumexp.
//   CTA: 32 anchors x all 16384 keys, key tiles of 64, K=128 resident.
//   256 threads, micro-tile 4 rows x 2 cols. smem [k][row] layout -> per k:
//   LDS.128 (A, broadcast) + LDS.64 (B, conflict-free) + 8 FFMA.
//   ce_i = m_i + log(sum_j exp(z_ij - m_i)) - z_ii,  m_i = |a_i|*10.
// ---------------------------------------------------------------------------
#define BM 32
#define BN 64
#define NTILES (M_KEYS / BN)

__global__ void __launch_bounds__(256) tcl_kernel(const float* __restrict__ hid) {
    __shared__ float sA[D * BM];   // 16 KB  [k][m], A pre-scaled by 1/temp
    __shared__ float sB[D * BN];   // 32 KB  [k][n]
    int tid  = threadIdx.x;
    int ty   = tid >> 5;           // 0..7  (warp id = row group)
    int tx   = tid & 31;           // lane  (col group)
    int row0 = blockIdx.x * BM;

    // Load anchor tile (rows are non-contiguous in hiddens: h = (a/3)*4 + a%3)
    {
        int r  = tid & 31;
        int kc = tid >> 5;                  // 8 chunks of 16 k
        int a  = row0 + r;
        int h  = (a / 3) * 4 + (a % 3);
        const float4* src = (const float4*)(hid + (size_t)h * D);
        #pragma unroll
        for (int i = 0; i < 4; i++) {
            int k = kc * 16 + i * 4;
            float4 v = src[k >> 2];
            sA[(k + 0) * BM + r] = v.x * INV_TEMP;
            sA[(k + 1) * BM + r] = v.y * INV_TEMP;
            sA[(k + 2) * BM + r] = v.z * INV_TEMP;
            sA[(k + 3) * BM + r] = v.w * INV_TEMP;
        }
    }

    float m[4];  int arow[4];
    float psum[4] = {0.f, 0.f, 0.f, 0.f};
    float zd[4]   = {0.f, 0.f, 0.f, 0.f};
    #pragma unroll
    for (int j = 0; j < 4; j++) {
        int a   = row0 + ty * 4 + j;
        arow[j] = a;
        int h   = (a / 3) * 4 + (a % 3);
        m[j]    = g_norm[h] * INV_TEMP;     // fixed shift (row max w/ huge margin)
    }

    int cB  = tid & 63;   // key col this thread loads
    int kcB = tid >> 6;   // 4 chunks of 32 k
    const float* pA = sA + ty * 4;
    const float* pB = sB + tx * 2;

    for (int t = 0; t < NTILES; t++) {
        __syncthreads();
        // Load 64-key tile (transposed into [k][n])
        {
            const float4* src = (const float4*)(g_keys + (size_t)(t * BN + cB) * D);
            #pragma unroll
            for (int i = 0; i < 8; i++) {
                int k = kcB * 32 + i * 4;
                float4 v = src[k >> 2];
                sB[(k + 0) * BN + cB] = v.x;
                sB[(k + 1) * BN + cB] = v.y;
                sB[(k + 2) * BN + cB] = v.z;
                sB[(k + 3) * BN + cB] = v.w;
            }
        }
        __syncthreads();

        float a00 = 0.f, a01 = 0.f, a10 = 0.f, a11 = 0.f;
        float a20 = 0.f, a21 = 0.f, a30 = 0.f, a31 = 0.f;
        #pragma unroll 16
        for (int k = 0; k < D; k++) {
            float4 av = *(const float4*)(pA + k * BM);
            float2 bv = *(const float2*)(pB + k * BN);
            a00 += av.x * bv.x;  a01 += av.x * bv.y;
            a10 += av.y * bv.x;  a11 += av.y * bv.y;
            a20 += av.z * bv.x;  a21 += av.z * bv.y;
            a30 += av.w * bv.x;  a31 += av.w * bv.y;
        }

        int kb = t * BN + tx * 2;
        float za[4][2] = {{a00, a01}, {a10, a11}, {a20, a21}, {a30, a31}};
        #pragma unroll
        for (int j = 0; j < 4; j++) {
            #pragma unroll
            for (int i = 0; i < 2; i++) {
                float z = za[j][i];
                psum[j] += __expf(z - m[j]);
                if (kb + i == arow[j]) zd[j] = z;   // diagonal: key col == anchor idx
            }
        }
    }

    // Warp (= row-group) reduction; exactly one lane contributed zd per row.
    #pragma unroll
    for (int j = 0; j < 4; j++) {
        float p = psum[j], z = zd[j];
        #pragma unroll
        for (int o = 16; o; o >>= 1) {
            p += __shfl_xor_sync(0xffffffffu, p, o);
            z += __shfl_xor_sync(0xffffffffu, z, o);
        }
        if (tx == 0) g_ce[arow[j]] = m[j] + logf(p) - z;
    }
}

// ---------------------------------------------------------------------------
// Kernel 4: deterministic finalize (single block).
// ---------------------------------------------------------------------------
__global__ void __launch_bounds__(256) finalize_kernel(const long long* __restrict__ targets,
                                                       float* __restrict__ out) {
    __shared__ float sce[256];
    __shared__ float scn[256];
    __shared__ float ssp[256];
    __shared__ float smm[256];
    int tid = threadIdx.x;

    float ce = 0.f, cnt = 0.f;
    for (int i = tid; i < N_ANCH; i += 256) {
        if (targets[i / 3] != 0) { ce += g_ce[i]; cnt += 1.f; }
    }
    float sp = 0.f, mm = 0.f;
    for (int i = tid; i < REG_BLOCKS; i += 256) { sp += g_psp[i]; mm += g_pmem[i]; }

    sce[tid] = ce; scn[tid] = cnt; ssp[tid] = sp; smm[tid] = mm;
    __syncthreads();
    for (int s = 128; s; s >>= 1) {
        if (tid < s) {
            sce[tid] += sce[tid + s]; scn[tid] += scn[tid + s];
            ssp[tid] += ssp[tid + s]; smm[tid] += smm[tid + s];
        }
        __syncthreads();
    }
    if (tid == 0) {
        float nv   = fmaxf(scn[0], 1.f);
        float tcl  = sce[0] / nv;
        float rate = ssp[0] / (float)TOTAL_ELEMS;
        float d    = rate - 0.02f;
        float sreg = d * d;
        float mreg = smm[0] / (float)TOTAL_ELEMS;
        out[0] = tcl + 0.01f * sreg + 0.001f * mreg;  // W_TCL=1
        out[1] = tcl;
        out[2] = sreg;
        out[3] = mreg;
        out[4] = rate;
    }
}

// ---------------------------------------------------------------------------
extern "C" void kernel_launch(void* const* d_in, const int* in_sizes, int n_in,
                              void* d_out, int out_size) {
    const float*     hid = (const float*)d_in[0];      // full_hiddens f32 [8,512,4,128]
    const long long* tg  = (const long long*)d_in[1];  // targets i64 [8,512]
    const float*     sp  = (const float*)d_in[2];      // spikes f32
    const float*     mem = (const float*)d_in[3];      // mem f32
    float* out = (float*)d_out;

    normalize_kernel<<<(M_KEYS * 32) / 256, 256>>>(hid);
    reg_kernel<<<REG_BLOCKS, 256>>>(sp, mem);
    tcl_kernel<<<N_ANCH / BM, 256>>>(hid);
    finalize_kernel<<<1, 256>>>(tg, out);
}

// round 5
// speedup vs baseline: 11.4087x; 11.4087x over previous
#include <cuda_runtime.h>
#include <cuda_bf16.h>
#include <cstdint>

#define D 128
#define M_KEYS 16384          // B*S*T
#define N_ANCH 12288          // B*S*(T-1)
#define TOTAL_ELEMS 2097152   // B*S*T*D
#define REG_BLOCKS 512
#define KEYSPLIT 8
#define KEYS_PER_SPLIT 2048
#define BM 128
#define BN 128
#define NT 16                 // KEYS_PER_SPLIT / BN
#define MTILES 96             // N_ANCH / BM
#define CE_BLOCKS 1536
#define SCALE 14.426950408889634f   // 10 * log2(e): base-2 exponent domain
#define LN2F 0.6931471805599453f
#define SMEM_DYN (99328 + 256)      // A(32K) + 2*B(32K) + ps(1K) + align slack

// Scratch (__device__ globals; allocation-free rule)
__device__ float         g_keys[M_KEYS * D];    // normalized keys fp32 (for exact diagonal)
__device__ __nv_bfloat16 g_keysb[M_KEYS * D];   // normalized keys bf16 (GEMM B)
__device__ __nv_bfloat16 g_anchb[N_ANCH * D];   // anchors * SCALE bf16 (GEMM A)
__device__ float g_norm[M_KEYS];
__device__ float g_psum[KEYSPLIT * N_ANCH];
__device__ float g_psp[REG_BLOCKS];
__device__ float g_pmem[REG_BLOCKS];
__device__ float g_cep[CE_BLOCKS];
__device__ float g_cnt[CE_BLOCKS];

__device__ __forceinline__ uint32_t su32(const void* p) {
    return (uint32_t)__cvta_generic_to_shared(p);
}
__device__ __forceinline__ float ex2f(float x) {
    float y; asm("ex2.approx.f32 %0, %1;" : "=f"(y) : "f"(x)); return y;
}
#define LDSM4(r, a) \
    asm volatile("ldmatrix.sync.aligned.m8n8.x4.shared.b16 {%0,%1,%2,%3}, [%4];" \
        : "=r"((r)[0]), "=r"((r)[1]), "=r"((r)[2]), "=r"((r)[3]) : "r"(a))
#define MMA_BF16(cr, a, b0v, b1v) \
    asm volatile("mma.sync.aligned.m16n8k16.row.col.f32.bf16.bf16.f32 " \
        "{%0,%1,%2,%3},{%4,%5,%6,%7},{%8,%9},{%0,%1,%2,%3};" \
        : "+f"((cr)[0]), "+f"((cr)[1]), "+f"((cr)[2]), "+f"((cr)[3]) \
        : "r"((a)[0]), "r"((a)[1]), "r"((a)[2]), "r"((a)[3]), "r"(b0v), "r"(b1v))
#define CP16(dst, src) \
    asm volatile("cp.async.cg.shared.global [%0], [%1], 16;" :: "r"(dst), "l"(src))
#define CP_COMMIT() asm volatile("cp.async.commit_group;" ::: "memory")

// ---------------------------------------------------------------------------
// Kernel 1: L2-normalize hidden rows; emit fp32 keys, bf16 keys, bf16 anchors.
// ---------------------------------------------------------------------------
__global__ void __launch_bounds__(256) normalize_kernel(const float* __restrict__ hid) {
    int row  = (blockIdx.x * blockDim.x + threadIdx.x) >> 5;
    int lane = threadIdx.x & 31;
    if (row >= M_KEYS) return;
    float4 v = ((const float4*)(hid + (size_t)row * D))[lane];
    float ss = v.x*v.x + v.y*v.y + v.z*v.z + v.w*v.w;
    #pragma unroll
    for (int o = 16; o; o >>= 1) ss += __shfl_xor_sync(0xffffffffu, ss, o);
    float nrm = fmaxf(sqrtf(ss), 1e-12f);
    float inv = 1.0f / nrm;
    float4 o4 = make_float4(v.x*inv, v.y*inv, v.z*inv, v.w*inv);
    ((float4*)(g_keys + (size_t)row * D))[lane] = o4;
    __nv_bfloat162* kb = (__nv_bfloat162*)(g_keysb + (size_t)row * D);
    kb[lane * 2 + 0] = __floats2bfloat162_rn(o4.x, o4.y);
    kb[lane * 2 + 1] = __floats2bfloat162_rn(o4.z, o4.w);
    if (lane == 0) g_norm[row] = nrm;
    int t = row & 3;
    if (t < 3) {
        int a = (row >> 2) * 3 + t;
        __nv_bfloat162* ab = (__nv_bfloat162*)(g_anchb + (size_t)a * D);
        ab[lane * 2 + 0] = __floats2bfloat162_rn(v.x * SCALE, v.y * SCALE);
        ab[lane * 2 + 1] = __floats2bfloat162_rn(v.z * SCALE, v.w * SCALE);
    }
}

// ---------------------------------------------------------------------------
// Kernel 2: spike sum + mem^2 sum partials (deterministic)
// ---------------------------------------------------------------------------
__global__ void __launch_bounds__(256) reg_kernel(const float* __restrict__ sp,
                                                  const float* __restrict__ mem) {
    __shared__ float s1[256], s2[256];
    int tid = threadIdx.x;
    float a = 0.f, b = 0.f;
    const int n4 = TOTAL_ELEMS / 4;
    for (int i = blockIdx.x * 256 + tid; i < n4; i += REG_BLOCKS * 256) {
        float4 v = ((const float4*)sp)[i];
        a += (v.x + v.y) + (v.z + v.w);
        float4 w = ((const float4*)mem)[i];
        b += (w.x*w.x + w.y*w.y) + (w.z*w.z + w.w*w.w);
    }
    s1[tid] = a; s2[tid] = b;
    __syncthreads();
    for (int s = 128; s; s >>= 1) {
        if (tid < s) { s1[tid] += s1[tid + s]; s2[tid] += s2[tid + s]; }
        __syncthreads();
    }
    if (tid == 0) { g_psp[blockIdx.x] = s1[0]; g_pmem[blockIdx.x] = s2[0]; }
}

// ---------------------------------------------------------------------------
// Kernel 3: bf16 mma.sync GEMM (128x128 CTA tile, K=128) fused with
// fixed-shift sum-of-exp2 epilogue. 8 warps (4x2), warp tile 32x64.
// A resident; B double-buffered via cp.async. XOR-swizzled smem (16B chunks).
// ---------------------------------------------------------------------------
__global__ void __launch_bounds__(256, 2) gemm_lse_kernel() {
    extern __shared__ char dyn[];
    char* base = (char*)(((uintptr_t)dyn + 255) & ~(uintptr_t)255);
    char* sA   = base;            // 32 KB
    char* sB0  = base + 32768;    // 32 KB
    char* sB1  = base + 65536;    // 32 KB
    float* s_ps = (float*)(base + 98304);  // 2 x 128 floats

    int tid  = threadIdx.x;
    int lane = tid & 31;
    int w    = tid >> 5;
    int wm   = w >> 1;            // 0..3 (M group)
    int wn   = w & 1;             // 0..1 (N group)
    int bx   = blockIdx.x;
    int ks   = bx / MTILES;
    int mt   = bx % MTILES;
    int m0   = mt * BM;
    int key0 = ks * KEYS_PER_SPLIT;

    // shift per owned row: rows r0+{0,8,16,24}, r0 = wm*32 + lane/4
    float m2v[4];
    #pragma unroll
    for (int j = 0; j < 4; j++) {
        int r = wm * 32 + (lane >> 2) + j * 8;
        int a = m0 + r;
        int h = (a / 3) * 4 + (a % 3);
        m2v[j] = g_norm[h] * SCALE;
    }

    int lrow = tid >> 1, lhalf = tid & 1;   // copy mapping: 2 threads/row, 8 chunks each
    // ---- A tile (once) + B tile 0: group 0 ----
    {
        const char* srcA = (const char*)(g_anchb + (size_t)(m0 + lrow) * D) + lhalf * 128;
        uint32_t dA = su32(sA) + lrow * 256;
        const char* srcB = (const char*)(g_keysb + (size_t)(key0 + lrow) * D) + lhalf * 128;
        uint32_t dB = su32(sB0) + lrow * 256;
        #pragma unroll
        for (int j = 0; j < 8; j++) {
            uint32_t cc = (uint32_t)(lhalf * 8 + j) ^ (uint32_t)(lrow & 7);
            CP16(dA + cc * 16, srcA + j * 16);
            CP16(dB + cc * 16, srcB + j * 16);
        }
        CP_COMMIT();
    }
    // ---- B tile 1: group 1 ----
    {
        const char* srcB = (const char*)(g_keysb + (size_t)(key0 + BN + lrow) * D) + lhalf * 128;
        uint32_t dB = su32(sB1) + lrow * 256;
        #pragma unroll
        for (int j = 0; j < 8; j++) {
            uint32_t cc = (uint32_t)(lhalf * 8 + j) ^ (uint32_t)(lrow & 7);
            CP16(dB + cc * 16, srcB + j * 16);
        }
        CP_COMMIT();
    }

    float ps[4] = {0.f, 0.f, 0.f, 0.f};
    // fragment address components (swizzle: chunk ^= row&7; all rows here share low3 = lane&7)
    uint32_t aRow  = su32(sA) + (uint32_t)(wm * 32 + (lane & 15)) * 256;
    uint32_t aSel  = (uint32_t)(lane >> 4);          // 0/1
    uint32_t bSel  = (uint32_t)((lane >> 3) & 1);    // 0/1
    uint32_t bRowO = (uint32_t)(wn * 64 + (lane & 7) + ((lane >> 4) & 1) * 8) * 256;
    uint32_t xr    = (uint32_t)(lane & 7);

    for (int t = 0; t < NT; t++) {
        if (t == NT - 1) asm volatile("cp.async.wait_group 0;" ::: "memory");
        else             asm volatile("cp.async.wait_group 1;" ::: "memory");
        __syncthreads();
        char* buf = (t & 1) ? sB1 : sB0;
        uint32_t bBase = su32(buf) + bRowO;

        float c[2][8][4];
        #pragma unroll
        for (int mi = 0; mi < 2; mi++)
            #pragma unroll
            for (int ni = 0; ni < 8; ni++)
                #pragma unroll
                for (int e = 0; e < 4; e++) c[mi][ni][e] = 0.f;

        #pragma unroll
        for (int kk = 0; kk < 8; kk++) {
            uint32_t ca = (((uint32_t)(2 * kk) + aSel) ^ xr) << 4;
            uint32_t cb = (((uint32_t)(2 * kk) + bSel) ^ xr) << 4;
            uint32_t a0[4], a1[4];
            LDSM4(a0, aRow + ca);
            LDSM4(a1, aRow + 16 * 256 + ca);
            #pragma unroll
            for (int nb = 0; nb < 4; nb++) {
                uint32_t bf[4];
                LDSM4(bf, bBase + (uint32_t)(nb * 16) * 256 + cb);
                MMA_BF16(c[0][2*nb + 0], a0, bf[0], bf[1]);
                MMA_BF16(c[0][2*nb + 1], a0, bf[2], bf[3]);
                MMA_BF16(c[1][2*nb + 0], a1, bf[0], bf[1]);
                MMA_BF16(c[1][2*nb + 1], a1, bf[2], bf[3]);
            }
        }
        __syncthreads();   // done reading buf; safe to overwrite
        if (t + 2 < NT) {
            const char* srcB = (const char*)(g_keysb +
                               (size_t)(key0 + (t + 2) * BN + lrow) * D) + lhalf * 128;
            uint32_t dB = su32((t & 1) ? sB1 : sB0) + lrow * 256;
            #pragma unroll
            for (int j = 0; j < 8; j++) {
                uint32_t cc = (uint32_t)(lhalf * 8 + j) ^ (uint32_t)(lrow & 7);
                CP16(dB + cc * 16, srcB + j * 16);
            }
            CP_COMMIT();
        }
        // epilogue: exp2(z - m2) accumulate (c rows: T/4 and T/4+8 per frag)
        #pragma unroll
        for (int mi = 0; mi < 2; mi++) {
            float mA = m2v[mi * 2 + 0], mB = m2v[mi * 2 + 1];
            #pragma unroll
            for (int ni = 0; ni < 8; ni++) {
                ps[mi*2 + 0] += ex2f(c[mi][ni][0] - mA) + ex2f(c[mi][ni][1] - mA);
                ps[mi*2 + 1] += ex2f(c[mi][ni][2] - mB) + ex2f(c[mi][ni][3] - mB);
            }
        }
    }

    // reduce across the 4 lanes sharing each row, then across the 2 N-warps
    #pragma unroll
    for (int j = 0; j < 4; j++) {
        float p = ps[j];
        p += __shfl_xor_sync(0xffffffffu, p, 1);
        p += __shfl_xor_sync(0xffffffffu, p, 2);
        if ((lane & 3) == 0) s_ps[wn * 128 + wm * 32 + (lane >> 2) + j * 8] = p;
    }
    __syncthreads();
    if (tid < 128)
        g_psum[ks * N_ANCH + m0 + tid] = s_ps[tid] + s_ps[128 + tid];
}

// ---------------------------------------------------------------------------
// Kernel 4: per-anchor CE (exact fp32 diagonal dot) + masked block partials
// ---------------------------------------------------------------------------
__global__ void __launch_bounds__(256) ce_kernel(const float* __restrict__ hid,
                                                 const long long* __restrict__ targets) {
    __shared__ float sc[8], scc[8];
    int tid = threadIdx.x, wid = tid >> 5, lane = tid & 31;
    int a = blockIdx.x * 8 + wid;
    int h = (a / 3) * 4 + (a % 3);
    float4 x = ((const float4*)(hid + (size_t)h * D))[lane];
    float4 k = ((const float4*)(g_keys + (size_t)a * D))[lane];
    float d = x.x*k.x + x.y*k.y + x.z*k.z + x.w*k.w;
    #pragma unroll
    for (int o = 16; o; o >>= 1) d += __shfl_xor_sync(0xffffffffu, d, o);
    if (lane == 0) {
        float P = 0.f;
        #pragma unroll
        for (int s = 0; s < KEYSPLIT; s++) P += g_psum[s * N_ANCH + a];
        float m2  = g_norm[h] * SCALE;
        float zd2 = d * SCALE;
        float ce  = LN2F * (m2 + __log2f(P) - zd2);
        bool valid = targets[a / 3] != 0;
        sc[wid]  = valid ? ce  : 0.f;
        scc[wid] = valid ? 1.f : 0.f;
    }
    __syncthreads();
    if (tid == 0) {
        float s = 0.f, c = 0.f;
        #pragma unroll
        for (int w = 0; w < 8; w++) { s += sc[w]; c += scc[w]; }
        g_cep[blockIdx.x] = s;
        g_cnt[blockIdx.x] = c;
    }
}

// ---------------------------------------------------------------------------
// Kernel 5: finalize
// ---------------------------------------------------------------------------
__global__ void __launch_bounds__(256) finalize_kernel(float* __restrict__ out) {
    __shared__ float sce[256], scn[256], ssp[256], smm[256];
    int tid = threadIdx.x;
    float ce = 0.f, cnt = 0.f, sp = 0.f, mm = 0.f;
    for (int i = tid; i < CE_BLOCKS; i += 256) { ce += g_cep[i]; cnt += g_cnt[i]; }
    for (int i = tid; i < REG_BLOCKS; i += 256) { sp += g_psp[i]; mm += g_pmem[i]; }
    sce[tid] = ce; scn[tid] = cnt; ssp[tid] = sp; smm[tid] = mm;
    __syncthreads();
    for (int s = 128; s; s >>= 1) {
        if (tid < s) {
            sce[tid] += sce[tid + s]; scn[tid] += scn[tid + s];
            ssp[tid] += ssp[tid + s]; smm[tid] += smm[tid + s];
        }
        __syncthreads();
    }
    if (tid == 0) {
        float nv   = fmaxf(scn[0], 1.f);
        float tcl  = sce[0] / nv;
        float rate = ssp[0] / (float)TOTAL_ELEMS;
        float dd   = rate - 0.02f;
        float sreg = dd * dd;
        float mreg = smm[0] / (float)TOTAL_ELEMS;
        out[0] = tcl + 0.01f * sreg + 0.001f * mreg;
        out[1] = tcl;
        out[2] = sreg;
        out[3] = mreg;
        out[4] = rate;
    }
}

// ---------------------------------------------------------------------------
extern "C" void kernel_launch(void* const* d_in, const int* in_sizes, int n_in,
                              void* d_out, int out_size) {
    const float*     hid = (const float*)d_in[0];
    const long long* tg  = (const long long*)d_in[1];
    const float*     sp  = (const float*)d_in[2];
    const float*     mem = (const float*)d_in[3];
    float* out = (float*)d_out;

    cudaFuncSetAttribute(gemm_lse_kernel,
                         cudaFuncAttributeMaxDynamicSharedMemorySize, SMEM_DYN);

    normalize_kernel<<<(M_KEYS * 32) / 256, 256>>>(hid);
    reg_kernel<<<REG_BLOCKS, 256>>>(sp, mem);
    gemm_lse_kernel<<<MTILES * KEYSPLIT, 256, SMEM_DYN>>>();
    ce_kernel<<<CE_BLOCKS, 256>>>(hid, tg);
    finalize_kernel<<<1, 256>>>(out);
}

// round 8
// speedup vs baseline: 12.3927x; 1.0863x over previous
#include <cuda_runtime.h>
#include <cuda_fp8.h>
#include <cstdint>

#define D 128
#define M_KEYS 16384          // B*S*T
#define N_ANCH 12288          // B*S*(T-1)
#define TOTAL_ELEMS 2097152   // B*S*T*D
#define REG_BLOCKS 512
#define KEYSPLIT 8
#define KEYS_PER_SPLIT 2048
#define BM 128
#define BN 128
#define NT 16                 // KEYS_PER_SPLIT / BN
#define MTILES 96             // N_ANCH / BM
#define CE_BLOCKS 1536
#define SCALE 14.426950408889634f   // 10 * log2(e): base-2 exponent domain
#define LN2F 0.6931471805599453f
#define RB 128                      // fp8 row bytes
#define SMEM_DYN (49152 + 1024 + 256)

// Scratch (__device__ globals; allocation-free rule)
__device__ float   g_keys[M_KEYS * D];     // normalized keys fp32 (exact CE positive)
__device__ uint8_t g_key8[M_KEYS * D];     // normalized keys e4m3 (GEMM B)
__device__ uint8_t g_anch8[N_ANCH * D];    // anchors * SCALE e4m3 (GEMM A)
__device__ float g_norm[M_KEYS];
__device__ float g_psum[KEYSPLIT * N_ANCH];
__device__ float g_psp[REG_BLOCKS];
__device__ float g_pmem[REG_BLOCKS];
__device__ float g_cep[CE_BLOCKS];
__device__ float g_cnt[CE_BLOCKS];

__device__ __forceinline__ uint32_t su32(const void* p) {
    return (uint32_t)__cvta_generic_to_shared(p);
}
__device__ __forceinline__ float ex2f(float x) {
    float y; asm("ex2.approx.f32 %0, %1;" : "=f"(y) : "f"(x)); return y;
}
__device__ __forceinline__ float fp8tof(uint32_t w, int j) {
    __nv_fp8_e4m3 e; e.__x = (__nv_fp8_storage_t)((w >> (8 * j)) & 0xFF);
    return (float)e;
}
#define LDSM4(r, a) \
    asm volatile("ldmatrix.sync.aligned.m8n8.x4.shared.b16 {%0,%1,%2,%3}, [%4];" \
        : "=r"((r)[0]), "=r"((r)[1]), "=r"((r)[2]), "=r"((r)[3]) : "r"(a))
#define MMA_FP8(cr, a, b0v, b1v) \
    asm volatile("mma.sync.aligned.m16n8k32.row.col.f32.e4m3.e4m3.f32 " \
        "{%0,%1,%2,%3},{%4,%5,%6,%7},{%8,%9},{%0,%1,%2,%3};" \
        : "+f"((cr)[0]), "+f"((cr)[1]), "+f"((cr)[2]), "+f"((cr)[3]) \
        : "r"((a)[0]), "r"((a)[1]), "r"((a)[2]), "r"((a)[3]), "r"(b0v), "r"(b1v))
#define CP16(dst, src) \
    asm volatile("cp.async.cg.shared.global [%0], [%1], 16;" :: "r"(dst), "l"(src))
#define CP_COMMIT() asm volatile("cp.async.commit_group;" ::: "memory")

// ---------------------------------------------------------------------------
// Kernel 1: L2-normalize hidden rows; emit fp32 keys, fp8 keys, fp8 anchors.
// ---------------------------------------------------------------------------
__global__ void __launch_bounds__(256) normalize_kernel(const float* __restrict__ hid) {
    int row  = (blockIdx.x * blockDim.x + threadIdx.x) >> 5;
    int lane = threadIdx.x & 31;
    if (row >= M_KEYS) return;
    float4 v = ((const float4*)(hid + (size_t)row * D))[lane];
    float ss = v.x*v.x + v.y*v.y + v.z*v.z + v.w*v.w;
    #pragma unroll
    for (int o = 16; o; o >>= 1) ss += __shfl_xor_sync(0xffffffffu, ss, o);
    float nrm = fmaxf(sqrtf(ss), 1e-12f);
    float inv = 1.0f / nrm;
    float4 o4 = make_float4(v.x*inv, v.y*inv, v.z*inv, v.w*inv);
    ((float4*)(g_keys + (size_t)row * D))[lane] = o4;
    __nv_fp8x4_e4m3 qk(o4);
    ((uint32_t*)(g_key8 + (size_t)row * D))[lane] = (uint32_t)qk.__x;
    if (lane == 0) g_norm[row] = nrm;
    int t = row & 3;
    if (t < 3) {
        int a = (row >> 2) * 3 + t;
        float4 s4 = make_float4(v.x * SCALE, v.y * SCALE, v.z * SCALE, v.w * SCALE);
        __nv_fp8x4_e4m3 qa(s4);
        ((uint32_t*)(g_anch8 + (size_t)a * D))[lane] = (uint32_t)qa.__x;
    }
}

// ---------------------------------------------------------------------------
// Kernel 2: spike sum + mem^2 sum partials (deterministic)
// ---------------------------------------------------------------------------
__global__ void __launch_bounds__(256) reg_kernel(const float* __restrict__ sp,
                                                  const float* __restrict__ mem) {
    __shared__ float s1[256], s2[256];
    int tid = threadIdx.x;
    float a = 0.f, b = 0.f;
    const int n4 = TOTAL_ELEMS / 4;
    for (int i = blockIdx.x * 256 + tid; i < n4; i += REG_BLOCKS * 256) {
        float4 v = ((const float4*)sp)[i];
        a += (v.x + v.y) + (v.z + v.w);
        float4 w = ((const float4*)mem)[i];
        b += (w.x*w.x + w.y*w.y) + (w.z*w.z + w.w*w.w);
    }
    s1[tid] = a; s2[tid] = b;
    __syncthreads();
    for (int s = 128; s; s >>= 1) {
        if (tid < s) { s1[tid] += s1[tid + s]; s2[tid] += s2[tid + s]; }
        __syncthreads();
    }
    if (tid == 0) { g_psp[blockIdx.x] = s1[0]; g_pmem[blockIdx.x] = s2[0]; }
}

// ---------------------------------------------------------------------------
// Kernel 3: fp8 mma.sync GEMM (128x128 CTA tile, K=128) fused with
// fixed-shift sum-of-exp2 epilogue. 8 warps (4x2), warp tile 32x64.
// A resident; B double-buffered via cp.async. XOR-swizzled 16B chunks.
// ---------------------------------------------------------------------------
__global__ void __launch_bounds__(256, 2) gemm_lse_kernel() {
    extern __shared__ char dyn[];
    char* base = (char*)(((uintptr_t)dyn + 255) & ~(uintptr_t)255);
    char* sA   = base;            // 16 KB
    char* sB0  = base + 16384;    // 16 KB
    char* sB1  = base + 32768;    // 16 KB
    float* s_ps = (float*)(base + 49152);  // 2 x 128 floats

    int tid  = threadIdx.x;
    int lane = tid & 31;
    int w    = tid >> 5;
    int wm   = w >> 1;            // 0..3 (M group)
    int wn   = w & 1;             // 0..1 (N group)
    int bx   = blockIdx.x;
    int ks   = bx / MTILES;
    int mt   = bx % MTILES;
    int m0   = mt * BM;
    int key0 = ks * KEYS_PER_SPLIT;

    float m2v[4];
    #pragma unroll
    for (int j = 0; j < 4; j++) {
        int r = wm * 32 + (lane >> 2) + j * 8;
        int a = m0 + r;
        int h = (a / 3) * 4 + (a % 3);
        m2v[j] = g_norm[h] * SCALE;
    }

    int lrow = tid >> 1, lhalf = tid & 1;   // 2 threads/row, 4 x 16B chunks each
    // ---- A tile (once) + B tile 0: group 0 ----
    {
        const char* srcA = (const char*)(g_anch8 + (size_t)(m0 + lrow) * D) + lhalf * 64;
        uint32_t dA = su32(sA) + lrow * RB;
        const char* srcB = (const char*)(g_key8 + (size_t)(key0 + lrow) * D) + lhalf * 64;
        uint32_t dB = su32(sB0) + lrow * RB;
        #pragma unroll
        for (int j = 0; j < 4; j++) {
            uint32_t cc = (uint32_t)(lhalf * 4 + j) ^ (uint32_t)(lrow & 7);
            CP16(dA + cc * 16, srcA + j * 16);
            CP16(dB + cc * 16, srcB + j * 16);
        }
        CP_COMMIT();
    }
    // ---- B tile 1: group 1 ----
    {
        const char* srcB = (const char*)(g_key8 + (size_t)(key0 + BN + lrow) * D) + lhalf * 64;
        uint32_t dB = su32(sB1) + lrow * RB;
        #pragma unroll
        for (int j = 0; j < 4; j++) {
            uint32_t cc = (uint32_t)(lhalf * 4 + j) ^ (uint32_t)(lrow & 7);
            CP16(dB + cc * 16, srcB + j * 16);
        }
        CP_COMMIT();
    }

    float ps[4] = {0.f, 0.f, 0.f, 0.f};
    uint32_t aRow  = su32(sA) + (uint32_t)(wm * 32 + (lane & 15)) * RB;
    uint32_t aSel  = (uint32_t)(lane >> 4);          // 0/1
    uint32_t bSel  = (uint32_t)((lane >> 3) & 1);    // 0/1
    uint32_t bRowO = (uint32_t)(wn * 64 + (lane & 7) + ((lane >> 4) & 1) * 8) * RB;
    uint32_t xr    = (uint32_t)(lane & 7);

    for (int t = 0; t < NT; t++) {
        if (t == NT - 1) asm volatile("cp.async.wait_group 0;" ::: "memory");
        else             asm volatile("cp.async.wait_group 1;" ::: "memory");
        __syncthreads();
        char* buf = (t & 1) ? sB1 : sB0;
        uint32_t bBase = su32(buf) + bRowO;

        float c[2][8][4];
        #pragma unroll
        for (int mi = 0; mi < 2; mi++)
            #pragma unroll
            for (int ni = 0; ni < 8; ni++)
                #pragma unroll
                for (int e = 0; e < 4; e++) c[mi][ni][e] = 0.f;

        #pragma unroll
        for (int kk = 0; kk < 4; kk++) {        // 4 x k32 = K128
            uint32_t ca = (((uint32_t)(2 * kk) + aSel) ^ xr) << 4;
            uint32_t cb = (((uint32_t)(2 * kk) + bSel) ^ xr) << 4;
            uint32_t a0[4], a1[4];
            LDSM4(a0, aRow + ca);
            LDSM4(a1, aRow + 16 * RB + ca);
            #pragma unroll
            for (int nb = 0; nb < 4; nb++) {
                uint32_t bf[4];
                LDSM4(bf, bBase + (uint32_t)(nb * 16) * RB + cb);
                MMA_FP8(c[0][2*nb + 0], a0, bf[0], bf[1]);
                MMA_FP8(c[0][2*nb + 1], a0, bf[2], bf[3]);
                MMA_FP8(c[1][2*nb + 0], a1, bf[0], bf[1]);
                MMA_FP8(c[1][2*nb + 1], a1, bf[2], bf[3]);
            }
        }
        __syncthreads();   // done reading buf; safe to overwrite
        if (t + 2 < NT) {
            const char* srcB = (const char*)(g_key8 +
                               (size_t)(key0 + (t + 2) * BN + lrow) * D) + lhalf * 64;
            uint32_t dB = su32((t & 1) ? sB1 : sB0) + lrow * RB;
            #pragma unroll
            for (int j = 0; j < 4; j++) {
                uint32_t cc = (uint32_t)(lhalf * 4 + j) ^ (uint32_t)(lrow & 7);
                CP16(dB + cc * 16, srcB + j * 16);
            }
            CP_COMMIT();
        }
        // epilogue: exp2(z - m2) accumulate
        #pragma unroll
        for (int mi = 0; mi < 2; mi++) {
            float mA = m2v[mi * 2 + 0], mB = m2v[mi * 2 + 1];
            #pragma unroll
            for (int ni = 0; ni < 8; ni++) {
                ps[mi*2 + 0] += ex2f(c[mi][ni][0] - mA) + ex2f(c[mi][ni][1] - mA);
                ps[mi*2 + 1] += ex2f(c[mi][ni][2] - mB) + ex2f(c[mi][ni][3] - mB);
            }
        }
    }

    #pragma unroll
    for (int j = 0; j < 4; j++) {
        float p = ps[j];
        p += __shfl_xor_sync(0xffffffffu, p, 1);
        p += __shfl_xor_sync(0xffffffffu, p, 2);
        if ((lane & 3) == 0) s_ps[wn * 128 + wm * 32 + (lane >> 2) + j * 8] = p;
    }
    __syncthreads();
    if (tid < 128)
        g_psum[ks * N_ANCH + m0 + tid] = s_ps[tid] + s_ps[128 + tid];
}

// ---------------------------------------------------------------------------
// Kernel 4: per-anchor CE with exact-max-column correction.
//   P_corr = P_gemm - 2^(r_h - m2) + 1,  r_h = fp8-dequant dot(a8, k8[h])
//   ce = ln2 * (m2 + log2(P_corr) - z_i * SCALE),  z_i exact fp32 dot.
// ---------------------------------------------------------------------------
__global__ void __launch_bounds__(256) ce_kernel(const float* __restrict__ hid,
                                                 const long long* __restrict__ targets) {
    __shared__ float sc[8], scc[8];
    int tid = threadIdx.x, wid = tid >> 5, lane = tid & 31;
    int a = blockIdx.x * 8 + wid;
    int h = (a / 3) * 4 + (a % 3);
    // exact CE positive: anchor (hid row h) . key[a] (fp32)
    float4 x = ((const float4*)(hid + (size_t)h * D))[lane];
    float4 k = ((const float4*)(g_keys + (size_t)a * D))[lane];
    float d = x.x*k.x + x.y*k.y + x.z*k.z + x.w*k.w;
    // fp8 replica of max-column dot: a8[a] . k8[h]
    uint32_t wa = ((const uint32_t*)(g_anch8 + (size_t)a * D))[lane];
    uint32_t wk = ((const uint32_t*)(g_key8 + (size_t)h * D))[lane];
    float r = fp8tof(wa,0)*fp8tof(wk,0) + fp8tof(wa,1)*fp8tof(wk,1)
            + fp8tof(wa,2)*fp8tof(wk,2) + fp8tof(wa,3)*fp8tof(wk,3);
    #pragma unroll
    for (int o = 16; o; o >>= 1) {
        d += __shfl_xor_sync(0xffffffffu, d, o);
        r += __shfl_xor_sync(0xffffffffu, r, o);
    }
    if (lane == 0) {
        float P = 0.f;
        #pragma unroll
        for (int s = 0; s < KEYSPLIT; s++) P += g_psum[s * N_ANCH + a];
        float m2 = g_norm[h] * SCALE;
        float Pc = P - ex2f(r - m2) + 1.0f;          // replace fp8 max term by exact 1
        Pc = fmaxf(Pc, 1e-30f);
        float ce = LN2F * (m2 + __log2f(Pc) - d * SCALE);
        bool valid = targets[a / 3] != 0;
        sc[wid]  = valid ? ce  : 0.f;
        scc[wid] = valid ? 1.f : 0.f;
    }
    __syncthreads();
    if (tid == 0) {
        float s = 0.f, c = 0.f;
        #pragma unroll
        for (int w = 0; w < 8; w++) { s += sc[w]; c += scc[w]; }
        g_cep[blockIdx.x] = s;
        g_cnt[blockIdx.x] = c;
    }
}

// ---------------------------------------------------------------------------
// Kernel 5: finalize (1024 threads to cut latency)
// ---------------------------------------------------------------------------
__global__ void __launch_bounds__(1024) finalize_kernel(float* __restrict__ out) {
    __shared__ float sce[1024], scn[1024], ssp[1024], smm[1024];
    int tid = threadIdx.x;
    float ce = 0.f, cnt = 0.f, sp = 0.f, mm = 0.f;
    for (int i = tid; i < CE_BLOCKS; i += 1024) { ce += g_cep[i]; cnt += g_cnt[i]; }
    for (int i = tid; i < REG_BLOCKS; i += 1024) { sp += g_psp[i]; mm += g_pmem[i]; }
    sce[tid] = ce; scn[tid] = cnt; ssp[tid] = sp; smm[tid] = mm;
    __syncthreads();
    for (int s = 512; s; s >>= 1) {
        if (tid < s) {
            sce[tid] += sce[tid + s]; scn[tid] += scn[tid + s];
            ssp[tid] += ssp[tid + s]; smm[tid] += smm[tid + s];
        }
        __syncthreads();
    }
    if (tid == 0) {
        float nv   = fmaxf(scn[0], 1.f);
        float tcl  = sce[0] / nv;
        float rate = ssp[0] / (float)TOTAL_ELEMS;
        float dd   = rate - 0.02f;
        float sreg = dd * dd;
        float mreg = smm[0] / (float)TOTAL_ELEMS;
        out[0] = tcl + 0.01f * sreg + 0.001f * mreg;
        out[1] = tcl;
        out[2] = sreg;
        out[3] = mreg;
        out[4] = rate;
    }
}

// ---------------------------------------------------------------------------
extern "C" void kernel_launch(void* const* d_in, const int* in_sizes, int n_in,
                              void* d_out, int out_size) {
    const float*     hid = (const float*)d_in[0];
    const long long* tg  = (const long long*)d_in[1];
    const float*     sp  = (const float*)d_in[2];
    const float*     mem = (const float*)d_in[3];
    float* out = (float*)d_out;

    cudaFuncSetAttribute(gemm_lse_kernel,
                         cudaFuncAttributeMaxDynamicSharedMemorySize, SMEM_DYN);

    normalize_kernel<<<(M_KEYS * 32) / 256, 256>>>(hid);
    reg_kernel<<<REG_BLOCKS, 256>>>(sp, mem);
    gemm_lse_kernel<<<MTILES * KEYSPLIT, 256, SMEM_DYN>>>();
    ce_kernel<<<CE_BLOCKS, 256>>>(hid, tg);
    finalize_kernel<<<1, 1024>>>(out);
}